// round 2
// baseline (speedup 1.0000x reference)
#include <cuda_runtime.h>
#include <cuda_bf16.h>
#include <math.h>

// Problem constants
#define NN 13
#define BB 2
#define TT 2048
#define DD 1024
#define ROW_F4 (DD / 4)          // 256 float4 per row
#define THREADS 256
#define EPS 1.1920928955078125e-07f   // FLT_EPSILON = jnp.finfo(f32).eps

// Dynamic smem layout (floats):
//   [0, 13*1024)              : 13 staged V rows (float4-aligned)
//   [13*1024, +13*8)          : per-warp partial sum-of-squares
//   [13*1024+104, +13*8)      : per-warp partial dot
#define SMEM_ROWS_F   (NN * DD)
#define SMEM_SS_OFF   (SMEM_ROWS_F)
#define SMEM_DP_OFF   (SMEM_ROWS_F + NN * 8)
#define SMEM_BYTES    ((SMEM_ROWS_F + 2 * NN * 8) * 4)

__global__ __launch_bounds__(THREADS, 4)
void attn_res_block_kernel(const float4* __restrict__ V,
                           const float4* __restrict__ rms_w,
                           const float4* __restrict__ w_proj,
                           float4* __restrict__ out)
{
    extern __shared__ float smem[];
    float4* srows = reinterpret_cast<float4*>(smem);   // [NN][ROW_F4]
    float*  s_ss  = smem + SMEM_SS_OFF;                // [NN][8]
    float*  s_dp  = smem + SMEM_DP_OFF;                // [NN][8]

    const int bt   = blockIdx.x;          // 0 .. B*T-1
    const int tid  = threadIdx.x;
    const int lane = tid & 31;
    const int wid  = tid >> 5;            // 0..7

    // Combined weight for this thread's 4 channels (rms_weight * w_proj)
    float4 rw = rms_w[tid];
    float4 wp = w_proj[tid];
    const float w0 = rw.x * wp.x;
    const float w1 = rw.y * wp.y;
    const float w2 = rw.z * wp.z;
    const float w3 = rw.w * wp.w;

    // Phase 1: stream 13 rows GMEM -> smem, computing per-row partials.
    // Per-row scalar partials are warp-reduced immediately so no 26-wide
    // register arrays survive the loop (keeps regs <= 64 for 4 CTAs/SM).
    const long base = (long)bt * ROW_F4 + tid;
    #pragma unroll
    for (int n = 0; n < NN; n++) {
        float4 x = V[(long)n * (BB * TT) * ROW_F4 + base];
        srows[n * ROW_F4 + tid] = x;                       // STS.128
        float s1 = x.x * x.x + x.y * x.y + x.z * x.z + x.w * x.w;
        float s2 = x.x * w0  + x.y * w1  + x.z * w2  + x.w * w3;
        #pragma unroll
        for (int off = 16; off > 0; off >>= 1) {
            s1 += __shfl_xor_sync(0xFFFFFFFFu, s1, off);
            s2 += __shfl_xor_sync(0xFFFFFFFFu, s2, off);
        }
        if (lane == 0) {
            s_ss[n * 8 + wid] = s1;
            s_dp[n * 8 + wid] = s2;
        }
    }
    __syncthreads();

    // Softmax over depth (redundant per thread; 13 elements — cheap).
    float a[NN];
    float mx = -INFINITY;
    #pragma unroll
    for (int n = 0; n < NN; n++) {
        float tss = 0.f, tdp = 0.f;
        #pragma unroll
        for (int k = 0; k < 8; k++) {
            tss += s_ss[n * 8 + k];
            tdp += s_dp[n * 8 + k];
        }
        float l = rsqrtf(tss * (1.0f / DD) + EPS) * tdp;
        a[n] = l;
        mx = fmaxf(mx, l);
    }
    float denom = 0.f;
    #pragma unroll
    for (int n = 0; n < NN; n++) {
        a[n] = __expf(a[n] - mx);
        denom += a[n];
    }
    const float inv = 1.0f / denom;

    // Phase 2: weighted sum of the UN-normalized rows from smem.
    float4 o = make_float4(0.f, 0.f, 0.f, 0.f);
    #pragma unroll
    for (int n = 0; n < NN; n++) {
        float4 x = srows[n * ROW_F4 + tid];                // LDS.128
        float an = a[n] * inv;
        o.x += an * x.x;
        o.y += an * x.y;
        o.z += an * x.z;
        o.w += an * x.w;
    }
    out[(long)bt * ROW_F4 + tid] = o;
}

extern "C" void kernel_launch(void* const* d_in, const int* in_sizes, int n_in,
                              void* d_out, int out_size)
{
    const float4* V      = (const float4*)d_in[0];   // [13,2,2048,1024] f32
    const float4* rms_w  = (const float4*)d_in[1];   // [1024] f32
    const float4* w_proj = (const float4*)d_in[2];   // [1024] f32
    float4* out          = (float4*)d_out;           // [2,2048,1024] f32

    // >48KB dynamic smem requires explicit opt-in (non-stream API, capture-safe)
    cudaFuncSetAttribute(attn_res_block_kernel,
                         cudaFuncAttributeMaxDynamicSharedMemorySize, SMEM_BYTES);

    attn_res_block_kernel<<<BB * TT, THREADS, SMEM_BYTES>>>(V, rms_w, w_proj, out);
}

// round 3
// speedup vs baseline: 1.1396x; 1.1396x over previous
#include <cuda_runtime.h>
#include <cuda_bf16.h>
#include <math.h>
#include <stdint.h>

// Problem constants
#define NN 13
#define BB 2
#define TT 2048
#define DD 1024
#define ROW_F4 (DD / 4)          // 256 float4 per row
#define THREADS 256
#define EPS 1.1920928955078125e-07f   // FLT_EPSILON = jnp.finfo(f32).eps

// Dynamic smem layout (floats):
//   [0, 13*1024)        : 13 staged V rows
//   [+0, +13*8)         : per-warp partial sum-of-squares
//   [+13*8, +2*13*8)    : per-warp partial dot
#define SMEM_ROWS_F   (NN * DD)
#define SMEM_SS_OFF   (SMEM_ROWS_F)
#define SMEM_DP_OFF   (SMEM_ROWS_F + NN * 8)
#define SMEM_BYTES    ((SMEM_ROWS_F + 2 * NN * 8) * 4)

__device__ __forceinline__ void cp_async16(uint32_t smem_addr, const void* gptr) {
    asm volatile("cp.async.cg.shared.global [%0], [%1], 16;\n"
                 :: "r"(smem_addr), "l"(gptr));
}

__global__ __launch_bounds__(THREADS, 4)
void attn_res_block_kernel(const float4* __restrict__ V,
                           const float4* __restrict__ rms_w,
                           const float4* __restrict__ w_proj,
                           float4* __restrict__ out)
{
    extern __shared__ float smem[];
    float4* srows = reinterpret_cast<float4*>(smem);   // [NN][ROW_F4]
    float*  s_ss  = smem + SMEM_SS_OFF;                // [NN][8]
    float*  s_dp  = smem + SMEM_DP_OFF;                // [NN][8]

    const int bt   = blockIdx.x;
    const int tid  = threadIdx.x;
    const int lane = tid & 31;
    const int wid  = tid >> 5;

    // Phase 0: issue ALL 13 row copies GMEM->SMEM asynchronously.
    // No destination registers -> no dependency chain -> MLP = 13.
    uint32_t srows_a;
    {
        uint64_t t;
        asm("cvta.to.shared.u64 %0, %1;" : "=l"(t) : "l"((void*)srows));
        srows_a = (uint32_t)t;
    }
    const float4* gbase = V + (long)bt * ROW_F4 + tid;
    #pragma unroll
    for (int n = 0; n < NN; n++) {
        cp_async16(srows_a + (uint32_t)(n * ROW_F4 + tid) * 16u,
                   (const void*)(gbase + (long)n * (BB * TT) * ROW_F4));
    }
    asm volatile("cp.async.commit_group;\n");

    // Combined weight for this thread's 4 channels (overlaps with copies)
    float4 rw = rms_w[tid];
    float4 wp = w_proj[tid];
    const float w0 = rw.x * wp.x;
    const float w1 = rw.y * wp.y;
    const float w2 = rw.z * wp.z;
    const float w3 = rw.w * wp.w;

    asm volatile("cp.async.wait_group 0;\n" ::: "memory");
    __syncthreads();

    // Phase 1: per-row partials from SMEM, immediate warp reduction.
    #pragma unroll
    for (int n = 0; n < NN; n++) {
        float4 x = srows[n * ROW_F4 + tid];
        float s1 = x.x * x.x + x.y * x.y + x.z * x.z + x.w * x.w;
        float s2 = x.x * w0  + x.y * w1  + x.z * w2  + x.w * w3;
        #pragma unroll
        for (int off = 16; off > 0; off >>= 1) {
            s1 += __shfl_xor_sync(0xFFFFFFFFu, s1, off);
            s2 += __shfl_xor_sync(0xFFFFFFFFu, s2, off);
        }
        if (lane == 0) {
            s_ss[n * 8 + wid] = s1;
            s_dp[n * 8 + wid] = s2;
        }
    }
    __syncthreads();

    // Softmax over depth (redundant per thread; 13 elems — cheap ALU).
    float a[NN];
    float mx = -INFINITY;
    #pragma unroll
    for (int n = 0; n < NN; n++) {
        float tss = 0.f, tdp = 0.f;
        #pragma unroll
        for (int k = 0; k < 8; k++) {
            tss += s_ss[n * 8 + k];
            tdp += s_dp[n * 8 + k];
        }
        float l = rsqrtf(tss * (1.0f / DD) + EPS) * tdp;
        a[n] = l;
        mx = fmaxf(mx, l);
    }
    float denom = 0.f;
    #pragma unroll
    for (int n = 0; n < NN; n++) {
        a[n] = __expf(a[n] - mx);
        denom += a[n];
    }
    const float inv = 1.0f / denom;

    // Phase 2: weighted sum of UN-normalized rows from SMEM.
    float4 o = make_float4(0.f, 0.f, 0.f, 0.f);
    #pragma unroll
    for (int n = 0; n < NN; n++) {
        float4 x = srows[n * ROW_F4 + tid];
        float an = a[n] * inv;
        o.x += an * x.x;
        o.y += an * x.y;
        o.z += an * x.z;
        o.w += an * x.w;
    }
    out[(long)bt * ROW_F4 + tid] = o;
}

extern "C" void kernel_launch(void* const* d_in, const int* in_sizes, int n_in,
                              void* d_out, int out_size)
{
    const float4* V      = (const float4*)d_in[0];   // [13,2,2048,1024] f32
    const float4* rms_w  = (const float4*)d_in[1];   // [1024] f32
    const float4* w_proj = (const float4*)d_in[2];   // [1024] f32
    float4* out          = (float4*)d_out;           // [2,2048,1024] f32

    cudaFuncSetAttribute(attn_res_block_kernel,
                         cudaFuncAttributeMaxDynamicSharedMemorySize, SMEM_BYTES);

    attn_res_block_kernel<<<BB * TT, THREADS, SMEM_BYTES>>>(V, rms_w, w_proj, out);
}